// round 2
// baseline (speedup 1.0000x reference)
#include <cuda_runtime.h>
#include <math.h>

#define BB 2
#define TT 2048
#define DIMM 1024
#define HH 16
#define DHH 64
#define DTT 32
#define MM (BB*TT)   /* 4096 rows */
#define EPSF 1.1920928955078125e-07f

// ---------------- scratch (no allocation allowed) ----------------
__device__ float g_x[MM * DIMM];        // RMSNormed input
__device__ float g_kv[MM * DIMM];       // softmax(k)*v, layout [b*T + l][h*64 + d]
__device__ float g_P[BB * HH * 64 * 64];// stage-A result [b][h][jj][d]
__device__ float g_load[MM * DIMM];     // loading, layout [b*T + t][h*64 + d]

// Accurate-under-fast-math sincos: reduce in double (value identical to the
// fp32 angle the reference feeds to cos/sin), then sincosf on a small arg.
__device__ __forceinline__ void sincos_acc(float ang, float* s, float* c) {
    const double TWO_PI = 6.283185307179586476925286766559;
    double da = (double)ang;
    da -= floor(da * (1.0 / TWO_PI)) * TWO_PI;   // [0, 2pi)
    sincosf((float)da, s, c);
}

// ---------------- K1: RMSNorm ----------------
__global__ void k_rmsnorm(const float* __restrict__ states, const float* __restrict__ lnw) {
    int row = blockIdx.x;
    int tid = threadIdx.x;                 // 256 threads, 4 floats each
    const float4* src = reinterpret_cast<const float4*>(states + (size_t)row * DIMM);
    float4 v = src[tid];
    float ss = v.x * v.x + v.y * v.y + v.z * v.z + v.w * v.w;
    #pragma unroll
    for (int o = 16; o > 0; o >>= 1) ss += __shfl_xor_sync(0xffffffffu, ss, o);
    __shared__ float wsum[8];
    if ((tid & 31) == 0) wsum[tid >> 5] = ss;
    __syncthreads();
    if (tid < 8) {
        float s2 = wsum[tid];
        #pragma unroll
        for (int o = 4; o > 0; o >>= 1) s2 += __shfl_xor_sync(0xffu, s2, o);
        if (tid == 0) wsum[0] = s2;
    }
    __syncthreads();
    float scale = rsqrtf(wsum[0] * (1.0f / DIMM) + EPSF);
    float4 w = reinterpret_cast<const float4*>(lnw)[tid];
    float4 o;
    o.x = v.x * scale * w.x; o.y = v.y * scale * w.y;
    o.z = v.z * scale * w.z; o.w = v.w * scale * w.w;
    reinterpret_cast<float4*>(g_x + (size_t)row * DIMM)[tid] = o;
}

// ---------------- K2: fused K+V GEMM, per-head softmax, kv = p*v ----------------
// Block: 64 rows x one head (64 cols) for BOTH Wk and Wv. 256 threads, 4x4 micro-tiles.
__global__ void k_kv(const float* __restrict__ Wk, const float* __restrict__ bk,
                     const float* __restrict__ Wv, const float* __restrict__ bv,
                     const int* __restrict__ mask) {
    const int rowBase = blockIdx.x * 64;
    const int hbase   = blockIdx.y * 64;
    const int tid = threadIdx.x;
    const int tx = tid & 15, ty = tid >> 4;

    __shared__ float As[16][64];
    __shared__ float Bks[16][64];
    __shared__ float Bvs[16][64];
    __shared__ float Sk[64][65];
    __shared__ float Sv[64][65];

    float acck[4][4] = {}, accv[4][4] = {};
    const int lr = tid >> 2, lk = (tid & 3) * 4;   // each thread: one float4 per tile

    for (int kt = 0; kt < DIMM; kt += 16) {
        float4 a  = *(const float4*)(g_x + (size_t)(rowBase + lr) * DIMM + kt + lk);
        float4 wk = *(const float4*)(Wk  + (size_t)(hbase  + lr) * DIMM + kt + lk);
        float4 wv = *(const float4*)(Wv  + (size_t)(hbase  + lr) * DIMM + kt + lk);
        As[lk+0][lr]=a.x;  As[lk+1][lr]=a.y;  As[lk+2][lr]=a.z;  As[lk+3][lr]=a.w;
        Bks[lk+0][lr]=wk.x;Bks[lk+1][lr]=wk.y;Bks[lk+2][lr]=wk.z;Bks[lk+3][lr]=wk.w;
        Bvs[lk+0][lr]=wv.x;Bvs[lk+1][lr]=wv.y;Bvs[lk+2][lr]=wv.z;Bvs[lk+3][lr]=wv.w;
        __syncthreads();
        #pragma unroll
        for (int kk = 0; kk < 16; kk++) {
            float4 a4 = *(const float4*)&As[kk][ty * 4];
            float4 k4 = *(const float4*)&Bks[kk][tx * 4];
            float4 v4 = *(const float4*)&Bvs[kk][tx * 4];
            float av[4] = {a4.x, a4.y, a4.z, a4.w};
            float kf[4] = {k4.x, k4.y, k4.z, k4.w};
            float vf[4] = {v4.x, v4.y, v4.z, v4.w};
            #pragma unroll
            for (int i = 0; i < 4; i++)
                #pragma unroll
                for (int j = 0; j < 4; j++) {
                    acck[i][j] += av[i] * kf[j];
                    accv[i][j] += av[i] * vf[j];
                }
        }
        __syncthreads();
    }

    // add biases, stage into smem
    float kb[4], vb[4];
    #pragma unroll
    for (int j = 0; j < 4; j++) { kb[j] = bk[hbase + tx*4 + j]; vb[j] = bv[hbase + tx*4 + j]; }
    #pragma unroll
    for (int i = 0; i < 4; i++)
        #pragma unroll
        for (int j = 0; j < 4; j++) {
            Sk[ty*4+i][tx*4+j] = acck[i][j] + kb[j];
            Sv[ty*4+i][tx*4+j] = accv[i][j] + vb[j];
        }
    __syncthreads();

    // per-row softmax over 64 head dims, then kv = p * v  (thread per row)
    if (tid < 64) {
        int row = rowBase + tid;
        float mval = (float)mask[row];
        float mx = -INFINITY;
        #pragma unroll 8
        for (int c = 0; c < 64; c++) { float l = Sk[tid][c] * mval; mx = fmaxf(mx, l); }
        float sum = 0.0f;
        #pragma unroll 8
        for (int c = 0; c < 64; c++) {
            float e = expf(Sk[tid][c] * mval - mx);
            Sk[tid][c] = e; sum += e;
        }
        float inv = 1.0f / sum;
        #pragma unroll 8
        for (int c = 0; c < 64; c++) Sk[tid][c] = Sk[tid][c] * inv * Sv[tid][c];
    }
    __syncthreads();

    // coalesced writeback
    for (int e = tid; e < 64 * 64; e += 256) {
        int r = e >> 6, c = e & 63;
        g_kv[(size_t)(rowBase + r) * DIMM + hbase + c] = Sk[r][c];
    }
}

// ---------------- K3a: zero P ----------------
__global__ void k_zeroP() {
    int i = blockIdx.x * blockDim.x + threadIdx.x;
    if (i < BB * HH * 64 * 64) g_P[i] = 0.0f;
}

// ---------------- K3: stage A:  P[b,h,jj,d] = sum_l F[l,jj] * kv[b,l,h,d] ----------------
// grid (bh=32, split=8); each block covers 256 l, atomicAdds its 64x64 partial.
__global__ void k_stageA(const float* __restrict__ angles) {
    const int bh = blockIdx.x;            // b*16 + h
    const int b = bh >> 4, h = bh & 15;
    const int lbase0 = blockIdx.y * 256;
    const int tid = threadIdx.x;
    const int tx = tid & 15, ty = tid >> 4;

    __shared__ float F[16][64];
    __shared__ float KVs[16][64];
    __shared__ float wsh[32];
    if (tid < 32) wsh[tid] = angles[tid];
    __syncthreads();

    float acc[4][4] = {};
    for (int sub = 0; sub < 16; sub++) {
        int lbase = lbase0 + sub * 16;
        // 512 sincos per subtile -> 2 per thread
        {
            int e = tid;       int ll = e >> 5, j = e & 31;
            float s, c; sincos_acc((float)(lbase + ll) * wsh[j], &s, &c);
            F[ll][j] = c; F[ll][32 + j] = s;
            e = tid + 256;     ll = e >> 5; j = e & 31;
            sincos_acc((float)(lbase + ll) * wsh[j], &s, &c);
            F[ll][j] = c; F[ll][32 + j] = s;
        }
        int ll2 = tid >> 4, d0 = (tid & 15) * 4;
        *(float4*)&KVs[ll2][d0] =
            *(const float4*)(g_kv + (size_t)(b * TT + lbase + ll2) * DIMM + h * DHH + d0);
        __syncthreads();
        #pragma unroll
        for (int l = 0; l < 16; l++) {
            float4 f4 = *(const float4*)&F[l][ty * 4];
            float4 k4 = *(const float4*)&KVs[l][tx * 4];
            float ff[4] = {f4.x, f4.y, f4.z, f4.w};
            float kk[4] = {k4.x, k4.y, k4.z, k4.w};
            #pragma unroll
            for (int i = 0; i < 4; i++)
                #pragma unroll
                for (int j = 0; j < 4; j++) acc[i][j] += ff[i] * kk[j];
        }
        __syncthreads();
    }
    float* Pp = g_P + (size_t)bh * 64 * 64;
    #pragma unroll
    for (int i = 0; i < 4; i++)
        #pragma unroll
        for (int j = 0; j < 4; j++)
            atomicAdd(&Pp[(ty*4 + i) * 64 + tx*4 + j], acc[i][j]);
}

// ---------------- K4: stage B: loading[b,t,h,d] = sum_jj G[t,h,jj] * P[b,h,jj,d] ----------------
// grid = M/32 blocks; each block: 32 t-rows, loop over 16 heads.
__global__ void k_stageB(const float* __restrict__ angles, const float* __restrict__ hdelta) {
    const int base = blockIdx.x * 32;     // global row = b*T + t
    const int b = base / TT;
    const int tid = threadIdx.x;
    const int tx = tid & 15, ty = tid >> 4;

    __shared__ float Ph[64][64];
    __shared__ float Gs[32][65];
    __shared__ float wsh[32];
    if (tid < 32) wsh[tid] = angles[tid];
    __syncthreads();

    for (int h = 0; h < HH; h++) {
        float dh = hdelta[h];
        for (int e = tid; e < 32 * 32; e += 256) {
            int tl = e >> 5, j = e & 31;
            int trow = base + tl - b * TT;
            float s, c; sincos_acc(((float)trow + dh) * wsh[j], &s, &c);
            Gs[tl][j]      = c * (1.0f / 32.0f);
            Gs[tl][32 + j] = s * (1.0f / 32.0f);
        }
        const float4* Psrc = (const float4*)(g_P + (size_t)(b * HH + h) * 64 * 64);
        float4* Pd = (float4*)Ph;
        for (int e = tid; e < 1024; e += 256) Pd[e] = Psrc[e];
        __syncthreads();

        float acc[2][4] = {};
        #pragma unroll
        for (int jj = 0; jj < 64; jj++) {
            float g0 = Gs[ty*2 + 0][jj];
            float g1 = Gs[ty*2 + 1][jj];
            float4 p = *(const float4*)&Ph[jj][tx * 4];
            acc[0][0] += g0*p.x; acc[0][1] += g0*p.y; acc[0][2] += g0*p.z; acc[0][3] += g0*p.w;
            acc[1][0] += g1*p.x; acc[1][1] += g1*p.y; acc[1][2] += g1*p.z; acc[1][3] += g1*p.w;
        }
        #pragma unroll
        for (int i = 0; i < 2; i++) {
            int row = base + ty*2 + i;
            float4 o = make_float4(acc[i][0], acc[i][1], acc[i][2], acc[i][3]);
            *(float4*)(g_load + (size_t)row * DIMM + h * DHH + tx * 4) = o;
        }
        __syncthreads();
    }
}

// ---------------- K5: output GEMM: out = loading @ Wo^T + bo ----------------
__global__ void k_out(const float* __restrict__ Wo, const float* __restrict__ bo,
                      float* __restrict__ out) {
    const int rowBase = blockIdx.x * 64;
    const int colBase = blockIdx.y * 64;
    const int tid = threadIdx.x;
    const int tx = tid & 15, ty = tid >> 4;

    __shared__ float As[16][64];
    __shared__ float Bs[16][64];
    float acc[4][4] = {};
    const int lr = tid >> 2, lk = (tid & 3) * 4;

    for (int kt = 0; kt < DIMM; kt += 16) {
        float4 a = *(const float4*)(g_load + (size_t)(rowBase + lr) * DIMM + kt + lk);
        float4 w = *(const float4*)(Wo     + (size_t)(colBase + lr) * DIMM + kt + lk);
        As[lk+0][lr]=a.x; As[lk+1][lr]=a.y; As[lk+2][lr]=a.z; As[lk+3][lr]=a.w;
        Bs[lk+0][lr]=w.x; Bs[lk+1][lr]=w.y; Bs[lk+2][lr]=w.z; Bs[lk+3][lr]=w.w;
        __syncthreads();
        #pragma unroll
        for (int kk = 0; kk < 16; kk++) {
            float4 a4 = *(const float4*)&As[kk][ty * 4];
            float4 b4 = *(const float4*)&Bs[kk][tx * 4];
            float av[4] = {a4.x, a4.y, a4.z, a4.w};
            float bv_[4] = {b4.x, b4.y, b4.z, b4.w};
            #pragma unroll
            for (int i = 0; i < 4; i++)
                #pragma unroll
                for (int j = 0; j < 4; j++) acc[i][j] += av[i] * bv_[j];
        }
        __syncthreads();
    }
    float4 bias = *(const float4*)(bo + colBase + tx * 4);
    #pragma unroll
    for (int i = 0; i < 4; i++) {
        float4 o = make_float4(acc[i][0] + bias.x, acc[i][1] + bias.y,
                               acc[i][2] + bias.z, acc[i][3] + bias.w);
        *(float4*)(out + (size_t)(rowBase + ty*4 + i) * DIMM + colBase + tx * 4) = o;
    }
}

// ---------------- launch ----------------
extern "C" void kernel_launch(void* const* d_in, const int* in_sizes, int n_in,
                              void* d_out, int out_size) {
    const float* states = (const float*)d_in[0];
    const int*   mask   = (const int*)  d_in[1];
    const float* lnw    = (const float*)d_in[2];
    const float* angles = (const float*)d_in[3];
    const float* hdelta = (const float*)d_in[4];
    // d_in[5] = Wq, d_in[6] = q_bias : mathematically dead (softmax row-sum == 1)
    const float* Wk = (const float*)d_in[7];
    const float* bk = (const float*)d_in[8];
    const float* Wv = (const float*)d_in[9];
    const float* bv = (const float*)d_in[10];
    const float* Wo = (const float*)d_in[11];
    const float* bo = (const float*)d_in[12];
    float* out = (float*)d_out;

    k_rmsnorm<<<MM, 256>>>(states, lnw);

    dim3 g2(MM / 64, HH);
    k_kv<<<g2, 256>>>(Wk, bk, Wv, bv, mask);

    k_zeroP<<<(BB * HH * 64 * 64) / 256, 256>>>();

    dim3 g3(BB * HH, 8);
    k_stageA<<<g3, 256>>>(angles);

    k_stageB<<<MM / 32, 256>>>(angles, hdelta);

    dim3 g5(MM / 64, DIMM / 64);
    k_out<<<g5, 256>>>(Wo, bo, out);
}

// round 6
// speedup vs baseline: 1.9192x; 1.9192x over previous
#include <cuda_runtime.h>
#include <cuda_bf16.h>
#include <math.h>
#include <stdint.h>

#define BB 2
#define TT 2048
#define DIMM 1024
#define HH 16
#define MM (BB*TT)
#define TKE 3072
#define NCH 48
#define EPSF 1.1920928955078125e-07f
#define GSMEM (3*32768)

__device__ __align__(256) __nv_bfloat16 g_xs[(size_t)MM * TKE];
__device__ __align__(256) __nv_bfloat16 g_wkv[(size_t)2048 * TKE];
__device__ __align__(256) __nv_bfloat16 g_wo[(size_t)1024 * TKE];
__device__ __align__(256) __nv_bfloat16 g_loads[(size_t)MM * TKE];
__device__ __align__(256) float g_pre[(size_t)MM * 2048];
__device__ __align__(256) float g_kv[(size_t)MM * DIMM];
__device__ __align__(256) float g_F[TT * 64];
__device__ __align__(256) float g_G[TT * HH * 64];
__device__ __align__(256) float g_P[BB * HH * 64 * 64];

__device__ __forceinline__ uint32_t smem_u32(const void* p) {
    uint32_t a;
    asm("{ .reg .u64 t; cvta.to.shared.u64 t, %1; cvt.u32.u64 %0, t; }" : "=r"(a) : "l"(p));
    return a;
}
__device__ __forceinline__ void cpa16(uint32_t d, const void* s) {
    asm volatile("cp.async.cg.shared.global [%0], [%1], 16;" :: "r"(d), "l"(s));
}
__device__ __forceinline__ void sincos_acc(float ang, float* s, float* c) {
    const double TWO_PI = 6.283185307179586476925286766559;
    double da = (double)ang;
    da -= floor(da * (1.0 / TWO_PI)) * TWO_PI;
    sincosf((float)da, s, c);
}
__device__ __forceinline__ void split2(float a, unsigned short* h, unsigned short* l) {
    __nv_bfloat16 hb = __float2bfloat16(a);
    __nv_bfloat16 lb = __float2bfloat16(a - __bfloat162float(hb));
    *h = __bfloat16_as_ushort(hb); *l = __bfloat16_as_ushort(lb);
}
__device__ __forceinline__ void store_tri_A(__nv_bfloat16* dst, float4 v) {
    float a[4] = {v.x, v.y, v.z, v.w};
    unsigned short hs[4], ls[4];
    #pragma unroll
    for (int j = 0; j < 4; j++) split2(a[j], &hs[j], &ls[j]);
    uint2 w0, w1, w2;
    w0.x = (uint32_t)hs[0] | ((uint32_t)hs[0] << 16);
    w0.y = (uint32_t)ls[0] | ((uint32_t)hs[1] << 16);
    w1.x = (uint32_t)hs[1] | ((uint32_t)ls[1] << 16);
    w1.y = (uint32_t)hs[2] | ((uint32_t)hs[2] << 16);
    w2.x = (uint32_t)ls[2] | ((uint32_t)hs[3] << 16);
    w2.y = (uint32_t)hs[3] | ((uint32_t)ls[3] << 16);
    uint2* d = (uint2*)dst; d[0] = w0; d[1] = w1; d[2] = w2;
}
__device__ __forceinline__ void store_tri_B(__nv_bfloat16* dst, float4 v) {
    float a[4] = {v.x, v.y, v.z, v.w};
    unsigned short hs[4], ls[4];
    #pragma unroll
    for (int j = 0; j < 4; j++) split2(a[j], &hs[j], &ls[j]);
    uint2 w0, w1, w2;
    w0.x = (uint32_t)hs[0] | ((uint32_t)ls[0] << 16);
    w0.y = (uint32_t)hs[0] | ((uint32_t)hs[1] << 16);
    w1.x = (uint32_t)ls[1] | ((uint32_t)hs[1] << 16);
    w1.y = (uint32_t)hs[2] | ((uint32_t)ls[2] << 16);
    w2.x = (uint32_t)hs[2] | ((uint32_t)hs[3] << 16);
    w2.y = (uint32_t)ls[3] | ((uint32_t)hs[3] << 16);
    uint2* d = (uint2*)dst; d[0] = w0; d[1] = w1; d[2] = w2;
}
__device__ __forceinline__ uint4 ldsm4(uint32_t a) {
    uint4 r;
    asm volatile("ldmatrix.sync.aligned.m8n8.x4.shared.b16 {%0,%1,%2,%3}, [%4];"
                 : "=r"(r.x), "=r"(r.y), "=r"(r.z), "=r"(r.w) : "r"(a));
    return r;
}
__device__ __forceinline__ void mma16816(float* c, uint4 a, uint32_t b0, uint32_t b1) {
    asm volatile("mma.sync.aligned.m16n8k16.row.col.f32.bf16.bf16.f32 "
                 "{%0,%1,%2,%3}, {%4,%5,%6,%7}, {%8,%9}, {%0,%1,%2,%3};"
                 : "+f"(c[0]), "+f"(c[1]), "+f"(c[2]), "+f"(c[3])
                 : "r"(a.x), "r"(a.y), "r"(a.z), "r"(a.w), "r"(b0), "r"(b1));
}

/* ---- weight conversion -> B-side triples ---- */
__global__ void __launch_bounds__(256) k_convw(const float* __restrict__ Wk,
                                               const float* __restrict__ Wv,
                                               const float* __restrict__ Wo) {
    int row = blockIdx.x, tid = threadIdx.x;
    const float* src; __nv_bfloat16* dst;
    if (row < 1024)      { src = Wk + (size_t)row * 1024;          dst = g_wkv + (size_t)row * TKE; }
    else if (row < 2048) { src = Wv + (size_t)(row - 1024) * 1024; dst = g_wkv + (size_t)row * TKE; }
    else                 { src = Wo + (size_t)(row - 2048) * 1024; dst = g_wo + (size_t)(row - 2048) * TKE; }
    float4 v = ((const float4*)src)[tid];
    store_tri_B(dst + 3 * (tid * 4), v);
}

/* ---- trig tables ---- */
__global__ void __launch_bounds__(256) k_trig(const float* __restrict__ angles,
                                              const float* __restrict__ hdelta) {
    int t = blockIdx.x, tid = threadIdx.x;
    __shared__ float w[32], hd[16];
    if (tid < 32) w[tid] = angles[tid];
    if (tid >= 32 && tid < 48) hd[tid - 32] = hdelta[tid - 32];
    __syncthreads();
    if (tid < 32) {
        float s, c; sincos_acc((float)t * w[tid], &s, &c);
        g_F[t * 64 + tid] = c; g_F[t * 64 + 32 + tid] = s;
    }
    for (int e = tid; e < 512; e += 256) {
        int h = e >> 5, j = e & 31;
        float s, c; sincos_acc(((float)t + hd[h]) * w[j], &s, &c);
        g_G[(size_t)(t * HH + h) * 64 + j]      = c * 0.03125f;
        g_G[(size_t)(t * HH + h) * 64 + 32 + j] = s * 0.03125f;
    }
}

/* ---- RMSNorm -> A'-side triples ---- */
__global__ void __launch_bounds__(256) k_rmsnorm(const float* __restrict__ states,
                                                 const float* __restrict__ lnw) {
    int row = blockIdx.x, tid = threadIdx.x;
    float4 v = ((const float4*)(states + (size_t)row * DIMM))[tid];
    float ss = v.x*v.x + v.y*v.y + v.z*v.z + v.w*v.w;
    #pragma unroll
    for (int o = 16; o > 0; o >>= 1) ss += __shfl_xor_sync(0xffffffffu, ss, o);
    __shared__ float wsum[8];
    if ((tid & 31) == 0) wsum[tid >> 5] = ss;
    __syncthreads();
    if (tid < 8) {
        float s2 = wsum[tid];
        #pragma unroll
        for (int o = 4; o > 0; o >>= 1) s2 += __shfl_xor_sync(0xffu, s2, o);
        if (tid == 0) wsum[0] = s2;
    }
    __syncthreads();
    float sc = rsqrtf(wsum[0] * (1.0f / DIMM) + EPSF);
    float4 w = ((const float4*)lnw)[tid];
    float4 o = make_float4(v.x*sc*w.x, v.y*sc*w.y, v.z*sc*w.z, v.w*sc*w.w);
    store_tri_A(g_xs + (size_t)row * TKE + 3 * (tid * 4), o);
}

/* ---- warp-MMA GEMM: C[M,N] = A'[M,K'] . B'[N,K']^T, 128x128 tiles ---- */
__global__ void __launch_bounds__(256) k_mma(int mode, float* __restrict__ outp,
                                             const float* __restrict__ bias) {
    extern __shared__ __align__(16) char smc[];
    const __nv_bfloat16* Ap = mode ? g_loads : g_xs;
    const __nv_bfloat16* Bp = mode ? g_wo : g_wkv;
    float* C = mode ? outp : g_pre;
    const int ldc = mode ? 1024 : 2048;
    const int tid = threadIdx.x;
    const int rowBase = blockIdx.x * 128, colBase = blockIdx.y * 128;
    uint32_t sb = smem_u32(smc);

    const int lr = tid >> 1, lsg = (tid & 1) * 4;
    const __nv_bfloat16* gA = Ap + (size_t)(rowBase + lr) * TKE + lsg * 8;
    const __nv_bfloat16* gB = Bp + (size_t)(colBase + lr) * TKE + lsg * 8;
    uint32_t sw[4];
    #pragma unroll
    for (int s = 0; s < 4; s++) {
        uint32_t o = lr * 128 + (lsg + s) * 16;
        sw[s] = o ^ ((o >> 3) & 0x70);
    }
    #define LOADC(c) do {                                                         \
        uint32_t stA = sb + ((c) % 3) * 32768, stB = stA + 16384;                 \
        const __nv_bfloat16* pa = gA + (size_t)(c) * 64;                          \
        const __nv_bfloat16* pb = gB + (size_t)(c) * 64;                          \
        cpa16(stA + sw[0], pa);      cpa16(stB + sw[0], pb);                      \
        cpa16(stA + sw[1], pa + 8);  cpa16(stB + sw[1], pb + 8);                  \
        cpa16(stA + sw[2], pa + 16); cpa16(stB + sw[2], pb + 16);                 \
        cpa16(stA + sw[3], pa + 24); cpa16(stB + sw[3], pb + 24);                 \
        asm volatile("cp.async.commit_group;" ::: "memory"); } while (0)

    const int w = tid >> 5, lane = tid & 31;
    const int wm = w & 1, wn = w >> 1;
    const int arow = wm * 64 + ((lane >> 3) & 1) * 8 + (lane & 7);
    const uint32_t akh = (lane >> 4) * 16;
    const uint32_t aSwz = (arow & 7) * 16;
    uint32_t aOff[4];
    #pragma unroll
    for (int mt = 0; mt < 4; mt++) aOff[mt] = (arow + mt * 16) * 128;
    const int bn = wn * 32 + ((lane >> 4) & 1) * 8 + (lane & 7);
    const uint32_t bkh = ((lane >> 3) & 1) * 16;
    const uint32_t bSwz = (bn & 7) * 16;
    uint32_t bOff[2];
    bOff[0] = bn * 128; bOff[1] = (bn + 16) * 128;

    float acc[4][4][4];
    #pragma unroll
    for (int i = 0; i < 4; i++)
        #pragma unroll
        for (int j = 0; j < 4; j++)
            #pragma unroll
            for (int q = 0; q < 4; q++) acc[i][j][q] = 0.0f;

    LOADC(0); LOADC(1); LOADC(2);
    for (int j = 0; j < NCH; j++) {
        int pend = NCH - 1 - j;
        if (pend >= 2)      asm volatile("cp.async.wait_group 2;" ::: "memory");
        else if (pend == 1) asm volatile("cp.async.wait_group 1;" ::: "memory");
        else                asm volatile("cp.async.wait_group 0;" ::: "memory");
        __syncthreads();
        uint32_t stA = sb + (j % 3) * 32768, stB = stA + 16384;
        #pragma unroll
        for (int ks = 0; ks < 4; ks++) {
            uint32_t ka = (ks * 32 + akh) ^ aSwz;
            uint32_t kb = (ks * 32 + bkh) ^ bSwz;
            uint4 Af[4];
            #pragma unroll
            for (int mt = 0; mt < 4; mt++) Af[mt] = ldsm4(stA + aOff[mt] + ka);
            uint4 B0 = ldsm4(stB + bOff[0] + kb);
            uint4 B1 = ldsm4(stB + bOff[1] + kb);
            uint32_t bb[4][2] = {{B0.x, B0.y}, {B0.z, B0.w}, {B1.x, B1.y}, {B1.z, B1.w}};
            #pragma unroll
            for (int mt = 0; mt < 4; mt++)
                #pragma unroll
                for (int nt = 0; nt < 4; nt++)
                    mma16816(acc[mt][nt], Af[mt], bb[nt][0], bb[nt][1]);
        }
        __syncthreads();
        if (j + 3 < NCH) LOADC(j + 3);
    }
    #undef LOADC

    const int crow0 = rowBase + wm * 64 + (lane >> 2);
    const int ccol0 = colBase + wn * 32 + (lane & 3) * 2;
    #pragma unroll
    for (int mt = 0; mt < 4; mt++) {
        #pragma unroll
        for (int nt = 0; nt < 4; nt++) {
            int row = crow0 + mt * 16, col = ccol0 + nt * 8;
            float b0 = 0.f, b1 = 0.f;
            if (bias) { b0 = bias[col]; b1 = bias[col + 1]; }
            float2 v0 = make_float2(acc[mt][nt][0] + b0, acc[mt][nt][1] + b1);
            float2 v1 = make_float2(acc[mt][nt][2] + b0, acc[mt][nt][3] + b1);
            *(float2*)(C + (size_t)row * ldc + col) = v0;
            *(float2*)(C + (size_t)(row + 8) * ldc + col) = v1;
        }
    }
}

/* ---- softmax(k*m) * v, warp per (row, head) ---- */
__global__ void __launch_bounds__(256) k_softkv(const float* __restrict__ bk,
                                                const float* __restrict__ bv,
                                                const int* __restrict__ mask) {
    int w = threadIdx.x >> 5, lane = threadIdx.x & 31;
    int idx = blockIdx.x * 8 + w; int row = idx >> 4, h = idx & 15;
    const float* pr = g_pre + (size_t)row * 2048 + h * 64;
    float m = (float)mask[row];
    float2 k2 = *(const float2*)(pr + lane * 2);
    float2 b2 = *(const float2*)(bk + h * 64 + lane * 2);
    float2 v2 = *(const float2*)(pr + 1024 + lane * 2);
    float2 vb = *(const float2*)(bv + h * 64 + lane * 2);
    float k0 = (k2.x + b2.x) * m, k1 = (k2.y + b2.y) * m;
    float mx = fmaxf(k0, k1);
    #pragma unroll
    for (int o = 16; o; o >>= 1) mx = fmaxf(mx, __shfl_xor_sync(0xffffffffu, mx, o));
    float e0 = expf(k0 - mx), e1 = expf(k1 - mx);
    float s = e0 + e1;
    #pragma unroll
    for (int o = 16; o; o >>= 1) s += __shfl_xor_sync(0xffffffffu, s, o);
    float inv = 1.0f / s;
    float2 o2 = make_float2(e0 * inv * (v2.x + vb.x), e1 * inv * (v2.y + vb.y));
    *(float2*)(g_kv + (size_t)row * 1024 + h * 64 + lane * 2) = o2;
}

__global__ void k_zeroP() {
    int i = blockIdx.x * blockDim.x + threadIdx.x;
    if (i < BB * HH * 64 * 64) g_P[i] = 0.0f;
}

/* ---- stage A: P[b,h,jj,d] = sum_l F[l,jj]*kv[b,l,h,d] ---- */
__global__ void __launch_bounds__(256) k_stageA() {
    const int bh = blockIdx.x, b = bh >> 4, h = bh & 15;
    const int lbase0 = blockIdx.y * 256;
    const int tid = threadIdx.x, tx = tid & 15, ty = tid >> 4;
    __shared__ __align__(16) float F[16][64];
    __shared__ __align__(16) float KV[16][64];
    float acc[4][4] = {};
    for (int sub = 0; sub < 16; sub++) {
        int lbase = lbase0 + sub * 16;
        *(float4*)&F[ty][tx*4]  = *(const float4*)(g_F + (size_t)(lbase + ty) * 64 + tx * 4);
        *(float4*)&KV[ty][tx*4] = *(const float4*)(g_kv + (size_t)(b * TT + lbase + ty) * DIMM + h * 64 + tx * 4);
        __syncthreads();
        #pragma unroll
        for (int l = 0; l < 16; l++) {
            float4 f4 = *(const float4*)&F[l][ty * 4];
            float4 k4 = *(const float4*)&KV[l][tx * 4];
            float ff[4] = {f4.x, f4.y, f4.z, f4.w};
            float kk[4] = {k4.x, k4.y, k4.z, k4.w};
            #pragma unroll
            for (int i = 0; i < 4; i++)
                #pragma unroll
                for (int j = 0; j < 4; j++) acc[i][j] += ff[i] * kk[j];
        }
        __syncthreads();
    }
    float* Pp = g_P + (size_t)bh * 4096;
    #pragma unroll
    for (int i = 0; i < 4; i++)
        #pragma unroll
        for (int j = 0; j < 4; j++)
            atomicAdd(&Pp[(ty*4 + i) * 64 + tx*4 + j], acc[i][j]);
}

/* ---- stage B: loading = G . P -> A'-side triples for output GEMM ---- */
__global__ void __launch_bounds__(256) k_stageB() {
    const int base = blockIdx.x * 32;
    const int b = base / TT, t0 = base - b * TT;
    const int tid = threadIdx.x, tx = tid & 15, ty = tid >> 4;
    __shared__ __align__(16) float Ph[64][64];
    __shared__ __align__(16) float Gs[32][68];   /* 68: row stride 272B, 16B-divisible */
    for (int h = 0; h < HH; h++) {
        for (int e = tid; e < 32 * 16; e += 256) {
            int tl = e >> 4, j4 = (e & 15) * 4;
            *(float4*)&Gs[tl][j4] = *(const float4*)(g_G + (size_t)((t0 + tl) * HH + h) * 64 + j4);
        }
        for (int e = tid; e < 1024; e += 256)
            ((float4*)Ph)[e] = ((const float4*)(g_P + (size_t)(b * HH + h) * 4096))[e];
        __syncthreads();
        float acc[2][4] = {};
        #pragma unroll
        for (int jj = 0; jj < 64; jj++) {
            float g0 = Gs[ty*2 + 0][jj];
            float g1 = Gs[ty*2 + 1][jj];
            float4 p = *(const float4*)&Ph[jj][tx * 4];
            acc[0][0] += g0*p.x; acc[0][1] += g0*p.y; acc[0][2] += g0*p.z; acc[0][3] += g0*p.w;
            acc[1][0] += g1*p.x; acc[1][1] += g1*p.y; acc[1][2] += g1*p.z; acc[1][3] += g1*p.w;
        }
        #pragma unroll
        for (int i = 0; i < 2; i++) {
            int row = base + ty*2 + i;
            float4 o = make_float4(acc[i][0], acc[i][1], acc[i][2], acc[i][3]);
            store_tri_A(g_loads + (size_t)row * TKE + 3 * (h * 64 + tx * 4), o);
        }
        __syncthreads();
    }
}

extern "C" void kernel_launch(void* const* d_in, const int* in_sizes, int n_in,
                              void* d_out, int out_size) {
    const float* states = (const float*)d_in[0];
    const int*   mask   = (const int*)  d_in[1];
    const float* lnw    = (const float*)d_in[2];
    const float* angles = (const float*)d_in[3];
    const float* hdelta = (const float*)d_in[4];
    const float* Wk = (const float*)d_in[7];
    const float* bk = (const float*)d_in[8];
    const float* Wv = (const float*)d_in[9];
    const float* bv = (const float*)d_in[10];
    const float* Wo = (const float*)d_in[11];
    const float* bo = (const float*)d_in[12];
    float* out = (float*)d_out;

    cudaFuncSetAttribute(k_mma, cudaFuncAttributeMaxDynamicSharedMemorySize, GSMEM);

    k_convw<<<3072, 256>>>(Wk, Wv, Wo);
    k_trig<<<TT, 256>>>(angles, hdelta);
    k_rmsnorm<<<MM, 256>>>(states, lnw);

    dim3 gkv(MM / 128, 2048 / 128);
    k_mma<<<gkv, 256, GSMEM>>>(0, nullptr, nullptr);

    k_softkv<<<MM * HH / 8, 256>>>(bk, bv, mask);

    k_zeroP<<<(BB * HH * 64 * 64) / 256, 256>>>();
    dim3 ga(BB * HH, 8);
    k_stageA<<<ga, 256>>>();
    k_stageB<<<MM / 32, 256>>>();

    dim3 go(MM / 128, DIMM / 128);
    k_mma<<<go, 256, GSMEM>>>(1, out, bo);
}

// round 8
// speedup vs baseline: 2.0657x; 1.0764x over previous
#include <cuda_runtime.h>
#include <cuda_bf16.h>
#include <math.h>
#include <stdint.h>

#define BB 2
#define TT 2048
#define DIMM 1024
#define HH 16
#define MM (BB*TT)
#define TKE 3072
#define NCH 48
#define EPSF 1.1920928955078125e-07f
#define GSMEM (3*32768)

__device__ __align__(256) __nv_bfloat16 g_xs[(size_t)MM * TKE];
__device__ __align__(256) __nv_bfloat16 g_wkv[(size_t)2048 * TKE];  /* head-interleaved [k_h|v_h] */
__device__ __align__(256) __nv_bfloat16 g_wo[(size_t)1024 * TKE];
__device__ __align__(256) __nv_bfloat16 g_loads[(size_t)MM * TKE];
__device__ __align__(256) float g_kv[(size_t)MM * DIMM];
__device__ __align__(256) float g_F[TT * 64];
__device__ __align__(256) float g_G[TT * HH * 64];
__device__ __align__(256) float g_P[BB * HH * 64 * 64];

__device__ __forceinline__ uint32_t smem_u32(const void* p) {
    uint32_t a;
    asm("{ .reg .u64 t; cvta.to.shared.u64 t, %1; cvt.u32.u64 %0, t; }" : "=r"(a) : "l"(p));
    return a;
}
__device__ __forceinline__ void cpa16(uint32_t d, const void* s) {
    asm volatile("cp.async.cg.shared.global [%0], [%1], 16;" :: "r"(d), "l"(s));
}
/* fp32 Cody-Waite 2pi reduction: P1 products exact (n has <=8 mantissa bits) */
__device__ __forceinline__ void sincos_cw(float ang, float* s, float* c) {
    const float INV2PI = 0.15915494309189535f;
    const float P1 = 6.28125f;
    const float P2 = 1.9353071795864769e-3f;
    float n = rintf(ang * INV2PI);
    float r = fmaf(-n, P1, ang);
    r = fmaf(-n, P2, r);
    sincosf(r, s, c);
}
__device__ __forceinline__ void split2(float a, unsigned short* h, unsigned short* l) {
    __nv_bfloat16 hb = __float2bfloat16(a);
    __nv_bfloat16 lb = __float2bfloat16(a - __bfloat162float(hb));
    *h = __bfloat16_as_ushort(hb); *l = __bfloat16_as_ushort(lb);
}
__device__ __forceinline__ void store_tri_A(__nv_bfloat16* dst, float4 v) {
    float a[4] = {v.x, v.y, v.z, v.w};
    unsigned short hs[4], ls[4];
    #pragma unroll
    for (int j = 0; j < 4; j++) split2(a[j], &hs[j], &ls[j]);
    uint2 w0, w1, w2;
    w0.x = (uint32_t)hs[0] | ((uint32_t)hs[0] << 16);
    w0.y = (uint32_t)ls[0] | ((uint32_t)hs[1] << 16);
    w1.x = (uint32_t)hs[1] | ((uint32_t)ls[1] << 16);
    w1.y = (uint32_t)hs[2] | ((uint32_t)hs[2] << 16);
    w2.x = (uint32_t)ls[2] | ((uint32_t)hs[3] << 16);
    w2.y = (uint32_t)hs[3] | ((uint32_t)ls[3] << 16);
    uint2* d = (uint2*)dst; d[0] = w0; d[1] = w1; d[2] = w2;
}
__device__ __forceinline__ void store_tri_B(__nv_bfloat16* dst, float4 v) {
    float a[4] = {v.x, v.y, v.z, v.w};
    unsigned short hs[4], ls[4];
    #pragma unroll
    for (int j = 0; j < 4; j++) split2(a[j], &hs[j], &ls[j]);
    uint2 w0, w1, w2;
    w0.x = (uint32_t)hs[0] | ((uint32_t)ls[0] << 16);
    w0.y = (uint32_t)hs[0] | ((uint32_t)hs[1] << 16);
    w1.x = (uint32_t)ls[1] | ((uint32_t)hs[1] << 16);
    w1.y = (uint32_t)hs[2] | ((uint32_t)ls[2] << 16);
    w2.x = (uint32_t)hs[2] | ((uint32_t)hs[3] << 16);
    w2.y = (uint32_t)ls[3] | ((uint32_t)hs[3] << 16);
    uint2* d = (uint2*)dst; d[0] = w0; d[1] = w1; d[2] = w2;
}
__device__ __forceinline__ uint4 ldsm4(uint32_t a) {
    uint4 r;
    asm volatile("ldmatrix.sync.aligned.m8n8.x4.shared.b16 {%0,%1,%2,%3}, [%4];"
                 : "=r"(r.x), "=r"(r.y), "=r"(r.z), "=r"(r.w) : "r"(a));
    return r;
}
__device__ __forceinline__ void mma16816(float* c, uint4 a, uint32_t b0, uint32_t b1) {
    asm volatile("mma.sync.aligned.m16n8k16.row.col.f32.bf16.bf16.f32 "
                 "{%0,%1,%2,%3}, {%4,%5,%6,%7}, {%8,%9}, {%0,%1,%2,%3};"
                 : "+f"(c[0]), "+f"(c[1]), "+f"(c[2]), "+f"(c[3])
                 : "r"(a.x), "r"(a.y), "r"(a.z), "r"(a.w), "r"(b0), "r"(b1));
}

/* ---- weight conversion -> B-side triples; KV rows head-interleaved ---- */
__global__ void __launch_bounds__(256) k_convw(const float* __restrict__ Wk,
                                               const float* __restrict__ Wv,
                                               const float* __restrict__ Wo) {
    int row = blockIdx.x, tid = threadIdx.x;
    const float* src; __nv_bfloat16* dst;
    if (row < 2048) {
        int h = row >> 7, c = row & 127;
        src = (c < 64) ? Wk + (size_t)(h * 64 + c) * 1024
                       : Wv + (size_t)(h * 64 + c - 64) * 1024;
        dst = g_wkv + (size_t)row * TKE;
    } else {
        src = Wo + (size_t)(row - 2048) * 1024;
        dst = g_wo + (size_t)(row - 2048) * TKE;
    }
    float4 v = ((const float4*)src)[tid];
    store_tri_B(dst + 3 * (tid * 4), v);
}

/* ---- trig tables ---- */
__global__ void __launch_bounds__(256) k_trig(const float* __restrict__ angles,
                                              const float* __restrict__ hdelta) {
    int t = blockIdx.x, tid = threadIdx.x;
    __shared__ float w[32], hd[16];
    if (tid < 32) w[tid] = angles[tid];
    if (tid >= 32 && tid < 48) hd[tid - 32] = hdelta[tid - 32];
    __syncthreads();
    if (tid < 32) {
        float s, c; sincos_cw((float)t * w[tid], &s, &c);
        g_F[t * 64 + tid] = c; g_F[t * 64 + 32 + tid] = s;
    }
    for (int e = tid; e < 512; e += 256) {
        int h = e >> 5, j = e & 31;
        float s, c; sincos_cw(((float)t + hd[h]) * w[j], &s, &c);
        g_G[(size_t)(t * HH + h) * 64 + j]      = c * 0.03125f;
        g_G[(size_t)(t * HH + h) * 64 + 32 + j] = s * 0.03125f;
    }
}

/* ---- RMSNorm -> A'-side triples ---- */
__global__ void __launch_bounds__(256) k_rmsnorm(const float* __restrict__ states,
                                                 const float* __restrict__ lnw) {
    int row = blockIdx.x, tid = threadIdx.x;
    float4 v = ((const float4*)(states + (size_t)row * DIMM))[tid];
    float ss = v.x*v.x + v.y*v.y + v.z*v.z + v.w*v.w;
    #pragma unroll
    for (int o = 16; o > 0; o >>= 1) ss += __shfl_xor_sync(0xffffffffu, ss, o);
    __shared__ float wsum[8];
    if ((tid & 31) == 0) wsum[tid >> 5] = ss;
    __syncthreads();
    if (tid < 8) {
        float s2 = wsum[tid];
        #pragma unroll
        for (int o = 4; o > 0; o >>= 1) s2 += __shfl_xor_sync(0xffu, s2, o);
        if (tid == 0) wsum[0] = s2;
    }
    __syncthreads();
    float sc = rsqrtf(wsum[0] * (1.0f / DIMM) + EPSF);
    float4 w = ((const float4*)lnw)[tid];
    float4 o = make_float4(v.x*sc*w.x, v.y*sc*w.y, v.z*sc*w.z, v.w*sc*w.w);
    store_tri_A(g_xs + (size_t)row * TKE + 3 * (tid * 4), o);
}

/* ---- warp-MMA GEMM, frag-pipelined; mode0 fuses softmax*v epilogue ---- */
__global__ void __launch_bounds__(256, 2) k_mma(int mode, float* __restrict__ outp,
                                                const float* __restrict__ bo,
                                                const float* __restrict__ bk,
                                                const float* __restrict__ bv,
                                                const int* __restrict__ mask) {
    extern __shared__ __align__(16) char smc[];
    __shared__ float bks[64], bvs[64];
    const __nv_bfloat16* Ap = mode ? g_loads : g_xs;
    const __nv_bfloat16* Bp = mode ? g_wo : g_wkv;
    const int tid = threadIdx.x;
    const int rowBase = blockIdx.x * 128, colBase = blockIdx.y * 128;
    uint32_t sb = smem_u32(smc);

    if (mode == 0) {
        if (tid < 64)            bks[tid]      = bk[blockIdx.y * 64 + tid];
        else if (tid < 128)      bvs[tid - 64] = bv[blockIdx.y * 64 + tid - 64];
    }

    const int lr = tid >> 1, lsg = (tid & 1) * 4;
    const __nv_bfloat16* gA = Ap + (size_t)(rowBase + lr) * TKE + lsg * 8;
    const __nv_bfloat16* gB = Bp + (size_t)(colBase + lr) * TKE + lsg * 8;
    uint32_t sw[4];
    #pragma unroll
    for (int s = 0; s < 4; s++) {
        uint32_t o = lr * 128 + (lsg + s) * 16;
        sw[s] = o ^ ((o >> 3) & 0x70);
    }
    #define LOADC(c) do {                                                         \
        uint32_t stA = sb + ((c) % 3) * 32768, stB = stA + 16384;                 \
        const __nv_bfloat16* pa = gA + (size_t)(c) * 64;                          \
        const __nv_bfloat16* pb = gB + (size_t)(c) * 64;                          \
        cpa16(stA + sw[0], pa);      cpa16(stB + sw[0], pb);                      \
        cpa16(stA + sw[1], pa + 8);  cpa16(stB + sw[1], pb + 8);                  \
        cpa16(stA + sw[2], pa + 16); cpa16(stB + sw[2], pb + 16);                 \
        cpa16(stA + sw[3], pa + 24); cpa16(stB + sw[3], pb + 24);                 \
        asm volatile("cp.async.commit_group;" ::: "memory"); } while (0)

    const int w = tid >> 5, lane = tid & 31;
    const int wm = w & 1, wn = w >> 1;
    const int arow = wm * 64 + ((lane >> 3) & 1) * 8 + (lane & 7);
    const uint32_t akh = (lane >> 4) * 16;
    const uint32_t aSwz = (arow & 7) * 16;
    uint32_t aOff[4];
    #pragma unroll
    for (int mt = 0; mt < 4; mt++) aOff[mt] = (arow + mt * 16) * 128;
    const int bn = wn * 32 + ((lane >> 4) & 1) * 8 + (lane & 7);
    const uint32_t bkh = ((lane >> 3) & 1) * 16;
    const uint32_t bSwz = (bn & 7) * 16;
    uint32_t bOff[2];
    bOff[0] = bn * 128; bOff[1] = (bn + 16) * 128;

    float acc[4][4][4];
    #pragma unroll
    for (int i = 0; i < 4; i++)
        #pragma unroll
        for (int j = 0; j < 4; j++)
            #pragma unroll
            for (int q = 0; q < 4; q++) acc[i][j][q] = 0.0f;

    uint4 Af[2][4]; uint4 Bf[2][2];
    #define LDFRAG(buf, stA, stB, ksv) do {                                       \
        uint32_t ka = ((ksv) * 32 + akh) ^ aSwz;                                  \
        uint32_t kb = ((ksv) * 32 + bkh) ^ bSwz;                                  \
        Af[buf][0] = ldsm4((stA) + aOff[0] + ka);                                 \
        Af[buf][1] = ldsm4((stA) + aOff[1] + ka);                                 \
        Af[buf][2] = ldsm4((stA) + aOff[2] + ka);                                 \
        Af[buf][3] = ldsm4((stA) + aOff[3] + ka);                                 \
        Bf[buf][0] = ldsm4((stB) + bOff[0] + kb);                                 \
        Bf[buf][1] = ldsm4((stB) + bOff[1] + kb); } while (0)

    LOADC(0); LOADC(1); LOADC(2);
    for (int j = 0; j < NCH; j++) {
        int pend = NCH - 1 - j;
        if (pend >= 2)      asm volatile("cp.async.wait_group 2;" ::: "memory");
        else if (pend == 1) asm volatile("cp.async.wait_group 1;" ::: "memory");
        else                asm volatile("cp.async.wait_group 0;" ::: "memory");
        __syncthreads();
        uint32_t stA = sb + (j % 3) * 32768, stB = stA + 16384;
        LDFRAG(0, stA, stB, 0);
        #pragma unroll
        for (int ks = 0; ks < 4; ks++) {
            if (ks < 3) LDFRAG((ks + 1) & 1, stA, stB, ks + 1);
            const int cb = ks & 1;
            uint32_t bb[4][2] = {{Bf[cb][0].x, Bf[cb][0].y}, {Bf[cb][0].z, Bf[cb][0].w},
                                 {Bf[cb][1].x, Bf[cb][1].y}, {Bf[cb][1].z, Bf[cb][1].w}};
            #pragma unroll
            for (int mt = 0; mt < 4; mt++)
                #pragma unroll
                for (int nt = 0; nt < 4; nt++)
                    mma16816(acc[mt][nt], Af[cb][mt], bb[nt][0], bb[nt][1]);
        }
        __syncthreads();
        if (j + 3 < NCH) LOADC(j + 3);
    }
    #undef LOADC
    #undef LDFRAG

    if (mode == 1) {
        const int crow0 = rowBase + wm * 64 + (lane >> 2);
        const int ccol0 = colBase + wn * 32 + (lane & 3) * 2;
        #pragma unroll
        for (int mt = 0; mt < 4; mt++) {
            #pragma unroll
            for (int nt = 0; nt < 4; nt++) {
                int row = crow0 + mt * 16, col = ccol0 + nt * 8;
                float b0 = bo[col], b1 = bo[col + 1];
                float2 v0 = make_float2(acc[mt][nt][0] + b0, acc[mt][nt][1] + b1);
                float2 v1 = make_float2(acc[mt][nt][2] + b0, acc[mt][nt][3] + b1);
                *(float2*)(outp + (size_t)row * 1024 + col) = v0;
                *(float2*)(outp + (size_t)(row + 8) * 1024 + col) = v1;
            }
        }
        return;
    }

    /* mode 0: stage scores to smem, per-row softmax(k)*v -> g_kv */
    float* Cs = (float*)smc;                  /* stride 129: conflict-free */
    const int lrow0 = wm * 64 + (lane >> 2);
    const int lcol0 = wn * 32 + (lane & 3) * 2;
    #pragma unroll
    for (int mt = 0; mt < 4; mt++) {
        #pragma unroll
        for (int nt = 0; nt < 4; nt++) {
            int rr = lrow0 + mt * 16, cc = lcol0 + nt * 8;
            Cs[rr * 129 + cc]           = acc[mt][nt][0];
            Cs[rr * 129 + cc + 1]       = acc[mt][nt][1];
            Cs[(rr + 8) * 129 + cc]     = acc[mt][nt][2];
            Cs[(rr + 8) * 129 + cc + 1] = acc[mt][nt][3];
        }
    }
    __syncthreads();
    {
        const int r = tid >> 1, half = tid & 1;
        float m = (float)mask[rowBase + r];
        float* crow = Cs + r * 129 + half * 32;       /* k: crow[0..31], v: crow[64..95] */
        const float* bkh_ = bks + half * 32;
        const float* bvh_ = bvs + half * 32;
        float mx = -INFINITY;
        #pragma unroll 8
        for (int i = 0; i < 32; i++) {
            float kk = (crow[i] + bkh_[i]) * m;
            crow[i] = kk; mx = fmaxf(mx, kk);
        }
        mx = fmaxf(mx, __shfl_xor_sync(0xffffffffu, mx, 1));
        float sum = 0.0f;
        #pragma unroll 8
        for (int i = 0; i < 32; i++) {
            float e = expf(crow[i] - mx);
            crow[i] = e; sum += e;
        }
        sum += __shfl_xor_sync(0xffffffffu, sum, 1);
        float inv = 1.0f / sum;
        float* dst = g_kv + (size_t)(rowBase + r) * 1024 + blockIdx.y * 64 + half * 32;
        #pragma unroll 8
        for (int i = 0; i < 32; i++)
            dst[i] = crow[i] * inv * (crow[64 + i] + bvh_[i]);
    }
}

__global__ void k_zeroP() {
    int i = blockIdx.x * blockDim.x + threadIdx.x;
    if (i < BB * HH * 64 * 64) g_P[i] = 0.0f;
}

/* ---- stage A: P[b,h,jj,d] = sum_l F[l,jj]*kv[b,l,h,d] ---- */
__global__ void __launch_bounds__(256) k_stageA() {
    const int bh = blockIdx.x, b = bh >> 4, h = bh & 15;
    const int lbase0 = blockIdx.y * 256;
    const int tid = threadIdx.x, tx = tid & 15, ty = tid >> 4;
    __shared__ __align__(16) float F[16][64];
    __shared__ __align__(16) float KV[16][64];
    float acc[4][4] = {};
    for (int sub = 0; sub < 16; sub++) {
        int lbase = lbase0 + sub * 16;
        *(float4*)&F[ty][tx*4]  = *(const float4*)(g_F + (size_t)(lbase + ty) * 64 + tx * 4);
        *(float4*)&KV[ty][tx*4] = *(const float4*)(g_kv + (size_t)(b * TT + lbase + ty) * DIMM + h * 64 + tx * 4);
        __syncthreads();
        #pragma unroll
        for (int l = 0; l < 16; l++) {
            float4 f4 = *(const float4*)&F[l][ty * 4];
            float4 k4 = *(const float4*)&KV[l][tx * 4];
            float ff[4] = {f4.x, f4.y, f4.z, f4.w};
            float kk[4] = {k4.x, k4.y, k4.z, k4.w};
            #pragma unroll
            for (int i = 0; i < 4; i++)
                #pragma unroll
                for (int j = 0; j < 4; j++) acc[i][j] += ff[i] * kk[j];
        }
        __syncthreads();
    }
    float* Pp = g_P + (size_t)bh * 4096;
    #pragma unroll
    for (int i = 0; i < 4; i++)
        #pragma unroll
        for (int j = 0; j < 4; j++)
            atomicAdd(&Pp[(ty*4 + i) * 64 + tx*4 + j], acc[i][j]);
}

/* ---- stage B: loading = G . P -> A'-side triples for output GEMM ---- */
__global__ void __launch_bounds__(256) k_stageB() {
    const int base = blockIdx.x * 32;
    const int b = base / TT, t0 = base - b * TT;
    const int tid = threadIdx.x, tx = tid & 15, ty = tid >> 4;
    __shared__ __align__(16) float Ph[64][64];
    __shared__ __align__(16) float Gs[32][68];
    for (int h = 0; h < HH; h++) {
        for (int e = tid; e < 32 * 16; e += 256) {
            int tl = e >> 4, j4 = (e & 15) * 4;
            *(float4*)&Gs[tl][j4] = *(const float4*)(g_G + (size_t)((t0 + tl) * HH + h) * 64 + j4);
        }
        for (int e = tid; e < 1024; e += 256)
            ((float4*)Ph)[e] = ((const float4*)(g_P + (size_t)(b * HH + h) * 4096))[e];
        __syncthreads();
        float acc[2][4] = {};
        #pragma unroll
        for (int jj = 0; jj < 64; jj++) {
            float g0 = Gs[ty*2 + 0][jj];
            float g1 = Gs[ty*2 + 1][jj];
            float4 p = *(const float4*)&Ph[jj][tx * 4];
            acc[0][0] += g0*p.x; acc[0][1] += g0*p.y; acc[0][2] += g0*p.z; acc[0][3] += g0*p.w;
            acc[1][0] += g1*p.x; acc[1][1] += g1*p.y; acc[1][2] += g1*p.z; acc[1][3] += g1*p.w;
        }
        #pragma unroll
        for (int i = 0; i < 2; i++) {
            int row = base + ty*2 + i;
            float4 o = make_float4(acc[i][0], acc[i][1], acc[i][2], acc[i][3]);
            store_tri_A(g_loads + (size_t)row * TKE + 3 * (h * 64 + tx * 4), o);
        }
        __syncthreads();
    }
}

extern "C" void kernel_launch(void* const* d_in, const int* in_sizes, int n_in,
                              void* d_out, int out_size) {
    const float* states = (const float*)d_in[0];
    const int*   mask   = (const int*)  d_in[1];
    const float* lnw    = (const float*)d_in[2];
    const float* angles = (const float*)d_in[3];
    const float* hdelta = (const float*)d_in[4];
    const float* Wk = (const float*)d_in[7];
    const float* bk = (const float*)d_in[8];
    const float* Wv = (const float*)d_in[9];
    const float* bv = (const float*)d_in[10];
    const float* Wo = (const float*)d_in[11];
    const float* bo = (const float*)d_in[12];
    float* out = (float*)d_out;

    cudaFuncSetAttribute(k_mma, cudaFuncAttributeMaxDynamicSharedMemorySize, GSMEM);

    k_convw<<<3072, 256>>>(Wk, Wv, Wo);
    k_trig<<<TT, 256>>>(angles, hdelta);
    k_rmsnorm<<<MM, 256>>>(states, lnw);

    dim3 gkv(MM / 128, HH);
    k_mma<<<gkv, 256, GSMEM>>>(0, nullptr, nullptr, bk, bv, mask);

    k_zeroP<<<(BB * HH * 64 * 64) / 256, 256>>>();
    dim3 ga(BB * HH, 8);
    k_stageA<<<ga, 256>>>();
    k_stageB<<<MM / 32, 256>>>();

    dim3 go(MM / 128, DIMM / 128);
    k_mma<<<go, 256, GSMEM>>>(1, out, bo, nullptr, nullptr, nullptr);
}

// round 9
// speedup vs baseline: 4.2067x; 2.0364x over previous
#include <cuda_runtime.h>
#include <cuda_fp16.h>
#include <math.h>
#include <stdint.h>

#define BB 2
#define TT 2048
#define DIMM 1024
#define HH 16
#define MM (BB*TT)
#define TKE 1024
#define NCH 16
#define EPSF 1.1920928955078125e-07f
#define GSMEM (3*32768)

__device__ __align__(256) __half g_xs[(size_t)MM * TKE];
__device__ __align__(256) __half g_wkv[(size_t)2048 * TKE];  /* head-interleaved [k_h|v_h] */
__device__ __align__(256) __half g_wo[(size_t)1024 * TKE];
__device__ __align__(256) __half g_loads[(size_t)MM * TKE];
__device__ __align__(256) float g_kv[(size_t)MM * DIMM];
__device__ __align__(256) float g_F[TT * 64];
__device__ __align__(256) float g_G[TT * HH * 64];
__device__ __align__(256) float g_P[BB * HH * 64 * 64];

__device__ __forceinline__ uint32_t smem_u32(const void* p) {
    uint32_t a;
    asm("{ .reg .u64 t; cvta.to.shared.u64 t, %1; cvt.u32.u64 %0, t; }" : "=r"(a) : "l"(p));
    return a;
}
__device__ __forceinline__ void cpa16(uint32_t d, const void* s) {
    asm volatile("cp.async.cg.shared.global [%0], [%1], 16;" :: "r"(d), "l"(s));
}
/* fp32 Cody-Waite 2pi reduction: P1 products exact (n has <=8 mantissa bits) */
__device__ __forceinline__ void sincos_cw(float ang, float* s, float* c) {
    const float INV2PI = 0.15915494309189535f;
    const float P1 = 6.28125f;
    const float P2 = 1.9353071795864769e-3f;
    float n = rintf(ang * INV2PI);
    float r = fmaf(-n, P1, ang);
    r = fmaf(-n, P2, r);
    sincosf(r, s, c);
}
__device__ __forceinline__ void store_h4(__half* dst, float4 v) {
    __half2* d = (__half2*)dst;
    d[0] = __floats2half2_rn(v.x, v.y);
    d[1] = __floats2half2_rn(v.z, v.w);
}
__device__ __forceinline__ uint4 ldsm4(uint32_t a) {
    uint4 r;
    asm volatile("ldmatrix.sync.aligned.m8n8.x4.shared.b16 {%0,%1,%2,%3}, [%4];"
                 : "=r"(r.x), "=r"(r.y), "=r"(r.z), "=r"(r.w) : "r"(a));
    return r;
}
__device__ __forceinline__ void mma16816(float* c, uint4 a, uint32_t b0, uint32_t b1) {
    asm volatile("mma.sync.aligned.m16n8k16.row.col.f32.f16.f16.f32 "
                 "{%0,%1,%2,%3}, {%4,%5,%6,%7}, {%8,%9}, {%0,%1,%2,%3};"
                 : "+f"(c[0]), "+f"(c[1]), "+f"(c[2]), "+f"(c[3])
                 : "r"(a.x), "r"(a.y), "r"(a.z), "r"(a.w), "r"(b0), "r"(b1));
}

/* ---- weight conversion -> fp16; KV rows head-interleaved ---- */
__global__ void __launch_bounds__(256) k_convw(const float* __restrict__ Wk,
                                               const float* __restrict__ Wv,
                                               const float* __restrict__ Wo) {
    int row = blockIdx.x, tid = threadIdx.x;
    const float* src; __half* dst;
    if (row < 2048) {
        int h = row >> 7, c = row & 127;
        src = (c < 64) ? Wk + (size_t)(h * 64 + c) * 1024
                       : Wv + (size_t)(h * 64 + c - 64) * 1024;
        dst = g_wkv + (size_t)row * TKE;
    } else {
        src = Wo + (size_t)(row - 2048) * 1024;
        dst = g_wo + (size_t)(row - 2048) * TKE;
    }
    float4 v = ((const float4*)src)[tid];
    store_h4(dst + tid * 4, v);
}

/* ---- trig tables ---- */
__global__ void __launch_bounds__(256) k_trig(const float* __restrict__ angles,
                                              const float* __restrict__ hdelta) {
    int t = blockIdx.x, tid = threadIdx.x;
    __shared__ float w[32], hd[16];
    if (tid < 32) w[tid] = angles[tid];
    if (tid >= 32 && tid < 48) hd[tid - 32] = hdelta[tid - 32];
    __syncthreads();
    if (tid < 32) {
        float s, c; sincos_cw((float)t * w[tid], &s, &c);
        g_F[t * 64 + tid] = c; g_F[t * 64 + 32 + tid] = s;
    }
    for (int e = tid; e < 512; e += 256) {
        int h = e >> 5, j = e & 31;
        float s, c; sincos_cw(((float)t + hd[h]) * w[j], &s, &c);
        g_G[(size_t)(t * HH + h) * 64 + j]      = c * 0.03125f;
        g_G[(size_t)(t * HH + h) * 64 + 32 + j] = s * 0.03125f;
    }
}

/* ---- RMSNorm -> fp16 A ---- */
__global__ void __launch_bounds__(256) k_rmsnorm(const float* __restrict__ states,
                                                 const float* __restrict__ lnw) {
    int row = blockIdx.x, tid = threadIdx.x;
    float4 v = ((const float4*)(states + (size_t)row * DIMM))[tid];
    float ss = v.x*v.x + v.y*v.y + v.z*v.z + v.w*v.w;
    #pragma unroll
    for (int o = 16; o > 0; o >>= 1) ss += __shfl_xor_sync(0xffffffffu, ss, o);
    __shared__ float wsum[8];
    if ((tid & 31) == 0) wsum[tid >> 5] = ss;
    __syncthreads();
    if (tid < 8) {
        float s2 = wsum[tid];
        #pragma unroll
        for (int o = 4; o > 0; o >>= 1) s2 += __shfl_xor_sync(0xffu, s2, o);
        if (tid == 0) wsum[0] = s2;
    }
    __syncthreads();
    float sc = rsqrtf(wsum[0] * (1.0f / DIMM) + EPSF);
    float4 w = ((const float4*)lnw)[tid];
    float4 o = make_float4(v.x*sc*w.x, v.y*sc*w.y, v.z*sc*w.z, v.w*sc*w.w);
    store_h4(g_xs + (size_t)row * TKE + tid * 4, o);
}

/* ---- warp-MMA GEMM (fp16), frag-pipelined; mode0 fuses softmax*v epilogue ---- */
__global__ void __launch_bounds__(256, 2) k_mma(int mode, float* __restrict__ outp,
                                                const float* __restrict__ bo,
                                                const float* __restrict__ bk,
                                                const float* __restrict__ bv,
                                                const int* __restrict__ mask) {
    extern __shared__ __align__(16) char smc[];
    __shared__ float bks[64], bvs[64];
    const __half* Ap = mode ? g_loads : g_xs;
    const __half* Bp = mode ? g_wo : g_wkv;
    const int tid = threadIdx.x;
    const int rowBase = blockIdx.x * 128, colBase = blockIdx.y * 128;
    uint32_t sb = smem_u32(smc);

    if (mode == 0) {
        if (tid < 64)            bks[tid]      = bk[blockIdx.y * 64 + tid];
        else if (tid < 128)      bvs[tid - 64] = bv[blockIdx.y * 64 + tid - 64];
    }

    const int lr = tid >> 1, lsg = (tid & 1) * 4;
    const __half* gA = Ap + (size_t)(rowBase + lr) * TKE + lsg * 8;
    const __half* gB = Bp + (size_t)(colBase + lr) * TKE + lsg * 8;
    uint32_t sw[4];
    #pragma unroll
    for (int s = 0; s < 4; s++) {
        uint32_t o = lr * 128 + (lsg + s) * 16;
        sw[s] = o ^ ((o >> 3) & 0x70);
    }
    #define LOADC(c) do {                                                         \
        uint32_t stA = sb + ((c) % 3) * 32768, stB = stA + 16384;                 \
        const __half* pa = gA + (size_t)(c) * 64;                                 \
        const __half* pb = gB + (size_t)(c) * 64;                                 \
        cpa16(stA + sw[0], pa);      cpa16(stB + sw[0], pb);                      \
        cpa16(stA + sw[1], pa + 8);  cpa16(stB + sw[1], pb + 8);                  \
        cpa16(stA + sw[2], pa + 16); cpa16(stB + sw[2], pb + 16);                 \
        cpa16(stA + sw[3], pa + 24); cpa16(stB + sw[3], pb + 24);                 \
        asm volatile("cp.async.commit_group;" ::: "memory"); } while (0)

    const int w = tid >> 5, lane = tid & 31;
    const int wm = w & 1, wn = w >> 1;
    const int arow = wm * 64 + ((lane >> 3) & 1) * 8 + (lane & 7);
    const uint32_t akh = (lane >> 4) * 16;
    const uint32_t aSwz = (arow & 7) * 16;
    uint32_t aOff[4];
    #pragma unroll
    for (int mt = 0; mt < 4; mt++) aOff[mt] = (arow + mt * 16) * 128;
    const int bn = wn * 32 + ((lane >> 4) & 1) * 8 + (lane & 7);
    const uint32_t bkh = ((lane >> 3) & 1) * 16;
    const uint32_t bSwz = (bn & 7) * 16;
    uint32_t bOff[2];
    bOff[0] = bn * 128; bOff[1] = (bn + 16) * 128;

    float acc[4][4][4];
    #pragma unroll
    for (int i = 0; i < 4; i++)
        #pragma unroll
        for (int j = 0; j < 4; j++)
            #pragma unroll
            for (int q = 0; q < 4; q++) acc[i][j][q] = 0.0f;

    uint4 Af[2][4]; uint4 Bf[2][2];
    #define LDFRAG(buf, stA, stB, ksv) do {                                       \
        uint32_t ka = ((ksv) * 32 + akh) ^ aSwz;                                  \
        uint32_t kb = ((ksv) * 32 + bkh) ^ bSwz;                                  \
        Af[buf][0] = ldsm4((stA) + aOff[0] + ka);                                 \
        Af[buf][1] = ldsm4((stA) + aOff[1] + ka);                                 \
        Af[buf][2] = ldsm4((stA) + aOff[2] + ka);                                 \
        Af[buf][3] = ldsm4((stA) + aOff[3] + ka);                                 \
        Bf[buf][0] = ldsm4((stB) + bOff[0] + kb);                                 \
        Bf[buf][1] = ldsm4((stB) + bOff[1] + kb); } while (0)

    LOADC(0); LOADC(1); LOADC(2);
    for (int j = 0; j < NCH; j++) {
        int pend = NCH - 1 - j;
        if (pend >= 2)      asm volatile("cp.async.wait_group 2;" ::: "memory");
        else if (pend == 1) asm volatile("cp.async.wait_group 1;" ::: "memory");
        else                asm volatile("cp.async.wait_group 0;" ::: "memory");
        __syncthreads();
        uint32_t stA = sb + (j % 3) * 32768, stB = stA + 16384;
        LDFRAG(0, stA, stB, 0);
        #pragma unroll
        for (int ks = 0; ks < 4; ks++) {
            if (ks < 3) LDFRAG((ks + 1) & 1, stA, stB, ks + 1);
            const int cb = ks & 1;
            uint32_t bb[4][2] = {{Bf[cb][0].x, Bf[cb][0].y}, {Bf[cb][0].z, Bf[cb][0].w},
                                 {Bf[cb][1].x, Bf[cb][1].y}, {Bf[cb][1].z, Bf[cb][1].w}};
            #pragma unroll
            for (int mt = 0; mt < 4; mt++)
                #pragma unroll
                for (int nt = 0; nt < 4; nt++)
                    mma16816(acc[mt][nt], Af[cb][mt], bb[nt][0], bb[nt][1]);
        }
        __syncthreads();
        if (j + 3 < NCH) LOADC(j + 3);
    }
    #undef LOADC
    #undef LDFRAG

    if (mode == 1) {
        const int crow0 = rowBase + wm * 64 + (lane >> 2);
        const int ccol0 = colBase + wn * 32 + (lane & 3) * 2;
        #pragma unroll
        for (int mt = 0; mt < 4; mt++) {
            #pragma unroll
            for (int nt = 0; nt < 4; nt++) {
                int row = crow0 + mt * 16, col = ccol0 + nt * 8;
                float b0 = bo[col], b1 = bo[col + 1];
                float2 v0 = make_float2(acc[mt][nt][0] + b0, acc[mt][nt][1] + b1);
                float2 v1 = make_float2(acc[mt][nt][2] + b0, acc[mt][nt][3] + b1);
                *(float2*)(outp + (size_t)row * 1024 + col) = v0;
                *(float2*)(outp + (size_t)(row + 8) * 1024 + col) = v1;
            }
        }
        return;
    }

    /* mode 0: stage scores to smem, per-row softmax(k)*v -> g_kv */
    float* Cs = (float*)smc;                  /* stride 129: conflict-free */
    const int lrow0 = wm * 64 + (lane >> 2);
    const int lcol0 = wn * 32 + (lane & 3) * 2;
    #pragma unroll
    for (int mt = 0; mt < 4; mt++) {
        #pragma unroll
        for (int nt = 0; nt < 4; nt++) {
            int rr = lrow0 + mt * 16, cc = lcol0 + nt * 8;
            Cs[rr * 129 + cc]           = acc[mt][nt][0];
            Cs[rr * 129 + cc + 1]       = acc[mt][nt][1];
            Cs[(rr + 8) * 129 + cc]     = acc[mt][nt][2];
            Cs[(rr + 8) * 129 + cc + 1] = acc[mt][nt][3];
        }
    }
    __syncthreads();
    {
        const int r = tid >> 1, half = tid & 1;
        float m = (float)mask[rowBase + r];
        float* crow = Cs + r * 129 + half * 32;       /* k: crow[0..31], v: crow[64..95] */
        const float* bkh_ = bks + half * 32;
        const float* bvh_ = bvs + half * 32;
        float mx = -INFINITY;
        #pragma unroll 8
        for (int i = 0; i < 32; i++) {
            float kk = (crow[i] + bkh_[i]) * m;
            crow[i] = kk; mx = fmaxf(mx, kk);
        }
        mx = fmaxf(mx, __shfl_xor_sync(0xffffffffu, mx, 1));
        float sum = 0.0f;
        #pragma unroll 8
        for (int i = 0; i < 32; i++) {
            float e = expf(crow[i] - mx);
            crow[i] = e; sum += e;
        }
        sum += __shfl_xor_sync(0xffffffffu, sum, 1);
        float inv = 1.0f / sum;
        float* dst = g_kv + (size_t)(rowBase + r) * 1024 + blockIdx.y * 64 + half * 32;
        #pragma unroll 8
        for (int i = 0; i < 32; i++)
            dst[i] = crow[i] * inv * (crow[64 + i] + bvh_[i]);
    }
}

__global__ void k_zeroP() {
    int i = blockIdx.x * blockDim.x + threadIdx.x;
    if (i < BB * HH * 64 * 64) g_P[i] = 0.0f;
}

/* ---- stage A: P[b,h,jj,d] = sum_l F[l,jj]*kv[b,l,h,d] ---- */
__global__ void __launch_bounds__(256) k_stageA() {
    const int bh = blockIdx.x, b = bh >> 4, h = bh & 15;
    const int lbase0 = blockIdx.y * 256;
    const int tid = threadIdx.x, tx = tid & 15, ty = tid >> 4;
    __shared__ __align__(16) float F[16][64];
    __shared__ __align__(16) float KV[16][64];
    float acc[4][4] = {};
    for (int sub = 0; sub < 16; sub++) {
        int lbase = lbase0 + sub * 16;
        *(float4*)&F[ty][tx*4]  = *(const float4*)(g_F + (size_t)(lbase + ty) * 64 + tx * 4);
        *(float4*)&KV[ty][tx*4] = *(const float4*)(g_kv + (size_t)(b * TT + lbase + ty) * DIMM + h * 64 + tx * 4);
        __syncthreads();
        #pragma unroll
        for (int l = 0; l < 16; l++) {
            float4 f4 = *(const float4*)&F[l][ty * 4];
            float4 k4 = *(const float4*)&KV[l][tx * 4];
            float ff[4] = {f4.x, f4.y, f4.z, f4.w};
            float kk[4] = {k4.x, k4.y, k4.z, k4.w};
            #pragma unroll
            for (int i = 0; i < 4; i++)
                #pragma unroll
                for (int j = 0; j < 4; j++) acc[i][j] += ff[i] * kk[j];
        }
        __syncthreads();
    }
    float* Pp = g_P + (size_t)bh * 4096;
    #pragma unroll
    for (int i = 0; i < 4; i++)
        #pragma unroll
        for (int j = 0; j < 4; j++)
            atomicAdd(&Pp[(ty*4 + i) * 64 + tx*4 + j], acc[i][j]);
}

/* ---- stage B: loading = G . P -> fp16 A for output GEMM ---- */
__global__ void __launch_bounds__(256) k_stageB() {
    const int base = blockIdx.x * 32;
    const int b = base / TT, t0 = base - b * TT;
    const int tid = threadIdx.x, tx = tid & 15, ty = tid >> 4;
    __shared__ __align__(16) float Ph[64][64];
    __shared__ __align__(16) float Gs[32][68];
    for (int h = 0; h < HH; h++) {
        for (int e = tid; e < 32 * 16; e += 256) {
            int tl = e >> 4, j4 = (e & 15) * 4;
            *(float4*)&Gs[tl][j4] = *(const float4*)(g_G + (size_t)((t0 + tl) * HH + h) * 64 + j4);
        }
        for (int e = tid; e < 1024; e += 256)
            ((float4*)Ph)[e] = ((const float4*)(g_P + (size_t)(b * HH + h) * 4096))[e];
        __syncthreads();
        float acc[2][4] = {};
        #pragma unroll
        for (int jj = 0; jj < 64; jj++) {
            float g0 = Gs[ty*2 + 0][jj];
            float g1 = Gs[ty*2 + 1][jj];
            float4 p = *(const float4*)&Ph[jj][tx * 4];
            acc[0][0] += g0*p.x; acc[0][1] += g0*p.y; acc[0][2] += g0*p.z; acc[0][3] += g0*p.w;
            acc[1][0] += g1*p.x; acc[1][1] += g1*p.y; acc[1][2] += g1*p.z; acc[1][3] += g1*p.w;
        }
        #pragma unroll
        for (int i = 0; i < 2; i++) {
            int row = base + ty*2 + i;
            float4 o = make_float4(acc[i][0], acc[i][1], acc[i][2], acc[i][3]);
            store_h4(g_loads + (size_t)row * TKE + h * 64 + tx * 4, o);
        }
        __syncthreads();
    }
}

extern "C" void kernel_launch(void* const* d_in, const int* in_sizes, int n_in,
                              void* d_out, int out_size) {
    const float* states = (const float*)d_in[0];
    const int*   mask   = (const int*)  d_in[1];
    const float* lnw    = (const float*)d_in[2];
    const float* angles = (const float*)d_in[3];
    const float* hdelta = (const float*)d_in[4];
    const float* Wk = (const float*)d_in[7];
    const float* bk = (const float*)d_in[8];
    const float* Wv = (const float*)d_in[9];
    const float* bv = (const float*)d_in[10];
    const float* Wo = (const float*)d_in[11];
    const float* bo = (const float*)d_in[12];
    float* out = (float*)d_out;

    cudaFuncSetAttribute(k_mma, cudaFuncAttributeMaxDynamicSharedMemorySize, GSMEM);

    k_convw<<<3072, 256>>>(Wk, Wv, Wo);
    k_trig<<<TT, 256>>>(angles, hdelta);
    k_rmsnorm<<<MM, 256>>>(states, lnw);

    dim3 gkv(MM / 128, HH);
    k_mma<<<gkv, 256, GSMEM>>>(0, nullptr, nullptr, bk, bv, mask);

    k_zeroP<<<(BB * HH * 64 * 64) / 256, 256>>>();
    dim3 ga(BB * HH, 8);
    k_stageA<<<ga, 256>>>();
    k_stageB<<<MM / 32, 256>>>();

    dim3 go(MM / 128, DIMM / 128);
    k_mma<<<go, 256, GSMEM>>>(1, out, bo, nullptr, nullptr, nullptr);
}

// round 10
// speedup vs baseline: 4.2991x; 1.0220x over previous
#include <cuda_runtime.h>
#include <cuda_fp16.h>
#include <math.h>
#include <stdint.h>

#define BB 2
#define TT 2048
#define DIMM 1024
#define HH 16
#define MM (BB*TT)
#define TKE 1024
#define NCH 16
#define EPSF 1.1920928955078125e-07f
#define GSMEM (3*32768)

__device__ __align__(256) __half g_xs[(size_t)MM * TKE];
__device__ __align__(256) __half g_wkv[(size_t)2048 * TKE];  /* head-interleaved [k_h|v_h] */
__device__ __align__(256) __half g_wo[(size_t)1024 * TKE];
__device__ __align__(256) __half g_loads[(size_t)MM * TKE];
__device__ __align__(256) float g_kv[(size_t)MM * DIMM];
__device__ __align__(256) float g_F[TT * 64];
__device__ __align__(256) float g_G[TT * HH * 64];
__device__ __align__(256) float g_P[BB * HH * 64 * 64];

__device__ __forceinline__ uint32_t smem_u32(const void* p) {
    uint32_t a;
    asm("{ .reg .u64 t; cvta.to.shared.u64 t, %1; cvt.u32.u64 %0, t; }" : "=r"(a) : "l"(p));
    return a;
}
__device__ __forceinline__ void cpa16(uint32_t d, const void* s) {
    asm volatile("cp.async.cg.shared.global [%0], [%1], 16;" :: "r"(d), "l"(s));
}
/* fp32 Cody-Waite 2pi reduction: P1 products exact (n has <=8 mantissa bits) */
__device__ __forceinline__ void sincos_cw(float ang, float* s, float* c) {
    const float INV2PI = 0.15915494309189535f;
    const float P1 = 6.28125f;
    const float P2 = 1.9353071795864769e-3f;
    float n = rintf(ang * INV2PI);
    float r = fmaf(-n, P1, ang);
    r = fmaf(-n, P2, r);
    sincosf(r, s, c);
}
__device__ __forceinline__ void store_h4(__half* dst, float4 v) {
    __half2* d = (__half2*)dst;
    d[0] = __floats2half2_rn(v.x, v.y);
    d[1] = __floats2half2_rn(v.z, v.w);
}
__device__ __forceinline__ uint4 ldsm4(uint32_t a) {
    uint4 r;
    asm volatile("ldmatrix.sync.aligned.m8n8.x4.shared.b16 {%0,%1,%2,%3}, [%4];"
                 : "=r"(r.x), "=r"(r.y), "=r"(r.z), "=r"(r.w) : "r"(a));
    return r;
}
__device__ __forceinline__ void mma16816(float* c, uint4 a, uint32_t b0, uint32_t b1) {
    asm volatile("mma.sync.aligned.m16n8k16.row.col.f32.f16.f16.f32 "
                 "{%0,%1,%2,%3}, {%4,%5,%6,%7}, {%8,%9}, {%0,%1,%2,%3};"
                 : "+f"(c[0]), "+f"(c[1]), "+f"(c[2]), "+f"(c[3])
                 : "r"(a.x), "r"(a.y), "r"(a.z), "r"(a.w), "r"(b0), "r"(b1));
}

/* ---- weight conversion -> fp16; KV rows head-interleaved ---- */
__global__ void __launch_bounds__(256) k_convw(const float* __restrict__ Wk,
                                               const float* __restrict__ Wv,
                                               const float* __restrict__ Wo) {
    int row = blockIdx.x, tid = threadIdx.x;
    const float* src; __half* dst;
    if (row < 2048) {
        int h = row >> 7, c = row & 127;
        src = (c < 64) ? Wk + (size_t)(h * 64 + c) * 1024
                       : Wv + (size_t)(h * 64 + c - 64) * 1024;
        dst = g_wkv + (size_t)row * TKE;
    } else {
        src = Wo + (size_t)(row - 2048) * 1024;
        dst = g_wo + (size_t)(row - 2048) * TKE;
    }
    float4 v = ((const float4*)src)[tid];
    store_h4(dst + tid * 4, v);
}

/* ---- trig tables ---- */
__global__ void __launch_bounds__(256) k_trig(const float* __restrict__ angles,
                                              const float* __restrict__ hdelta) {
    int t = blockIdx.x, tid = threadIdx.x;
    __shared__ float w[32], hd[16];
    if (tid < 32) w[tid] = angles[tid];
    if (tid >= 32 && tid < 48) hd[tid - 32] = hdelta[tid - 32];
    __syncthreads();
    if (tid < 32) {
        float s, c; sincos_cw((float)t * w[tid], &s, &c);
        g_F[t * 64 + tid] = c; g_F[t * 64 + 32 + tid] = s;
    }
    for (int e = tid; e < 512; e += 256) {
        int h = e >> 5, j = e & 31;
        float s, c; sincos_cw(((float)t + hd[h]) * w[j], &s, &c);
        g_G[(size_t)(t * HH + h) * 64 + j]      = c * 0.03125f;
        g_G[(size_t)(t * HH + h) * 64 + 32 + j] = s * 0.03125f;
    }
}

/* ---- RMSNorm -> fp16 A ---- */
__global__ void __launch_bounds__(256) k_rmsnorm(const float* __restrict__ states,
                                                 const float* __restrict__ lnw) {
    int row = blockIdx.x, tid = threadIdx.x;
    float4 v = ((const float4*)(states + (size_t)row * DIMM))[tid];
    float ss = v.x*v.x + v.y*v.y + v.z*v.z + v.w*v.w;
    #pragma unroll
    for (int o = 16; o > 0; o >>= 1) ss += __shfl_xor_sync(0xffffffffu, ss, o);
    __shared__ float wsum[8];
    if ((tid & 31) == 0) wsum[tid >> 5] = ss;
    __syncthreads();
    if (tid < 8) {
        float s2 = wsum[tid];
        #pragma unroll
        for (int o = 4; o > 0; o >>= 1) s2 += __shfl_xor_sync(0xffu, s2, o);
        if (tid == 0) wsum[0] = s2;
    }
    __syncthreads();
    float sc = rsqrtf(wsum[0] * (1.0f / DIMM) + EPSF);
    float4 w = ((const float4*)lnw)[tid];
    float4 o = make_float4(v.x*sc*w.x, v.y*sc*w.y, v.z*sc*w.z, v.w*sc*w.w);
    store_h4(g_xs + (size_t)row * TKE + tid * 4, o);
}

/* ---- warp-MMA GEMM (fp16), single-sync pipeline; mode0 fuses softmax*v ---- */
__global__ void __launch_bounds__(256, 2) k_mma(int mode, float* __restrict__ outp,
                                                const float* __restrict__ bo,
                                                const float* __restrict__ bk,
                                                const float* __restrict__ bv,
                                                const int* __restrict__ mask) {
    extern __shared__ __align__(16) char smc[];
    __shared__ float bks[64], bvs[64];
    const __half* Ap = mode ? g_loads : g_xs;
    const __half* Bp = mode ? g_wo : g_wkv;
    const int tid = threadIdx.x;
    const int rowBase = blockIdx.x * 128, colBase = blockIdx.y * 128;
    uint32_t sb = smem_u32(smc);

    if (mode == 0) {
        if (tid < 64)            bks[tid]      = bk[blockIdx.y * 64 + tid];
        else if (tid < 128)      bvs[tid - 64] = bv[blockIdx.y * 64 + tid - 64];
    }

    const int lr = tid >> 1, lsg = (tid & 1) * 4;
    const __half* gA = Ap + (size_t)(rowBase + lr) * TKE + lsg * 8;
    const __half* gB = Bp + (size_t)(colBase + lr) * TKE + lsg * 8;
    uint32_t sw[4];
    #pragma unroll
    for (int s = 0; s < 4; s++) {
        uint32_t o = lr * 128 + (lsg + s) * 16;
        sw[s] = o ^ ((o >> 3) & 0x70);
    }
    #define LOADC(c) do {                                                         \
        uint32_t stA = sb + ((c) % 3) * 32768, stB = stA + 16384;                 \
        const __half* pa = gA + (size_t)(c) * 64;                                 \
        const __half* pb = gB + (size_t)(c) * 64;                                 \
        cpa16(stA + sw[0], pa);      cpa16(stB + sw[0], pb);                      \
        cpa16(stA + sw[1], pa + 8);  cpa16(stB + sw[1], pb + 8);                  \
        cpa16(stA + sw[2], pa + 16); cpa16(stB + sw[2], pb + 16);                 \
        cpa16(stA + sw[3], pa + 24); cpa16(stB + sw[3], pb + 24);                 \
        asm volatile("cp.async.commit_group;" ::: "memory"); } while (0)

    const int w = tid >> 5, lane = tid & 31;
    const int wm = w & 1, wn = w >> 1;
    const int arow = wm * 64 + ((lane >> 3) & 1) * 8 + (lane & 7);
    const uint32_t akh = (lane >> 4) * 16;
    const uint32_t aSwz = (arow & 7) * 16;
    uint32_t aOff[4];
    #pragma unroll
    for (int mt = 0; mt < 4; mt++) aOff[mt] = (arow + mt * 16) * 128;
    const int bn = wn * 32 + ((lane >> 4) & 1) * 8 + (lane & 7);
    const uint32_t bkh = ((lane >> 3) & 1) * 16;
    const uint32_t bSwz = (bn & 7) * 16;
    uint32_t bOff[2];
    bOff[0] = bn * 128; bOff[1] = (bn + 16) * 128;

    float acc[4][4][4];
    #pragma unroll
    for (int i = 0; i < 4; i++)
        #pragma unroll
        for (int j = 0; j < 4; j++)
            #pragma unroll
            for (int q = 0; q < 4; q++) acc[i][j][q] = 0.0f;

    uint4 Af[2][4]; uint4 Bf[2][2];
    #define LDFRAG(buf, stA, stB, ksv) do {                                       \
        uint32_t ka = ((ksv) * 32 + akh) ^ aSwz;                                  \
        uint32_t kb = ((ksv) * 32 + bkh) ^ bSwz;                                  \
        Af[buf][0] = ldsm4((stA) + aOff[0] + ka);                                 \
        Af[buf][1] = ldsm4((stA) + aOff[1] + ka);                                 \
        Af[buf][2] = ldsm4((stA) + aOff[2] + ka);                                 \
        Af[buf][3] = ldsm4((stA) + aOff[3] + ka);                                 \
        Bf[buf][0] = ldsm4((stB) + bOff[0] + kb);                                 \
        Bf[buf][1] = ldsm4((stB) + bOff[1] + kb); } while (0)

    /* single-sync pipeline: prefetch distance 2, one barrier per chunk */
    LOADC(0); LOADC(1);
    for (int j = 0; j < NCH; j++) {
        if (j < NCH - 1) asm volatile("cp.async.wait_group 1;" ::: "memory");
        else             asm volatile("cp.async.wait_group 0;" ::: "memory");
        __syncthreads();
        uint32_t stA = sb + (j % 3) * 32768, stB = stA + 16384;
        if (j + 2 < NCH) LOADC(j + 2);   /* writes stage (j-1)%3: consumed last iter */
        LDFRAG(0, stA, stB, 0);
        #pragma unroll
        for (int ks = 0; ks < 4; ks++) {
            if (ks < 3) LDFRAG((ks + 1) & 1, stA, stB, ks + 1);
            const int cb = ks & 1;
            uint32_t bb[4][2] = {{Bf[cb][0].x, Bf[cb][0].y}, {Bf[cb][0].z, Bf[cb][0].w},
                                 {Bf[cb][1].x, Bf[cb][1].y}, {Bf[cb][1].z, Bf[cb][1].w}};
            #pragma unroll
            for (int mt = 0; mt < 4; mt++)
                #pragma unroll
                for (int nt = 0; nt < 4; nt++)
                    mma16816(acc[mt][nt], Af[cb][mt], bb[nt][0], bb[nt][1]);
        }
    }
    #undef LOADC
    #undef LDFRAG

    if (mode == 1) {
        const int crow0 = rowBase + wm * 64 + (lane >> 2);
        const int ccol0 = colBase + wn * 32 + (lane & 3) * 2;
        #pragma unroll
        for (int mt = 0; mt < 4; mt++) {
            #pragma unroll
            for (int nt = 0; nt < 4; nt++) {
                int row = crow0 + mt * 16, col = ccol0 + nt * 8;
                float b0 = bo[col], b1 = bo[col + 1];
                float2 v0 = make_float2(acc[mt][nt][0] + b0, acc[mt][nt][1] + b1);
                float2 v1 = make_float2(acc[mt][nt][2] + b0, acc[mt][nt][3] + b1);
                *(float2*)(outp + (size_t)row * 1024 + col) = v0;
                *(float2*)(outp + (size_t)(row + 8) * 1024 + col) = v1;
            }
        }
        return;
    }

    /* mode 0: stage scores to smem, per-row softmax(k)*v -> g_kv */
    __syncthreads();   /* all warps done with smem stages before reuse as Cs */
    float* Cs = (float*)smc;                  /* stride 129: conflict-free */
    const int lrow0 = wm * 64 + (lane >> 2);
    const int lcol0 = wn * 32 + (lane & 3) * 2;
    #pragma unroll
    for (int mt = 0; mt < 4; mt++) {
        #pragma unroll
        for (int nt = 0; nt < 4; nt++) {
            int rr = lrow0 + mt * 16, cc = lcol0 + nt * 8;
            Cs[rr * 129 + cc]           = acc[mt][nt][0];
            Cs[rr * 129 + cc + 1]       = acc[mt][nt][1];
            Cs[(rr + 8) * 129 + cc]     = acc[mt][nt][2];
            Cs[(rr + 8) * 129 + cc + 1] = acc[mt][nt][3];
        }
    }
    __syncthreads();
    {
        const int r = tid >> 1, half = tid & 1;
        float m = (float)mask[rowBase + r];
        float* crow = Cs + r * 129 + half * 32;       /* k: crow[0..31], v: crow[64..95] */
        const float* bkh_ = bks + half * 32;
        const float* bvh_ = bvs + half * 32;
        float mx = -INFINITY;
        #pragma unroll 8
        for (int i = 0; i < 32; i++) {
            float kk = (crow[i] + bkh_[i]) * m;
            crow[i] = kk; mx = fmaxf(mx, kk);
        }
        mx = fmaxf(mx, __shfl_xor_sync(0xffffffffu, mx, 1));
        float sum = 0.0f;
        #pragma unroll 8
        for (int i = 0; i < 32; i++) {
            float e = expf(crow[i] - mx);
            crow[i] = e; sum += e;
        }
        sum += __shfl_xor_sync(0xffffffffu, sum, 1);
        float inv = 1.0f / sum;
        float* dst = g_kv + (size_t)(rowBase + r) * 1024 + blockIdx.y * 64 + half * 32;
        #pragma unroll 8
        for (int i = 0; i < 32; i++)
            dst[i] = crow[i] * inv * (crow[64 + i] + bvh_[i]);
    }
}

__global__ void k_zeroP() {
    int i = blockIdx.x * blockDim.x + threadIdx.x;
    if (i < BB * HH * 64 * 64) g_P[i] = 0.0f;
}

/* ---- stage A: P[b,h,jj,d] = sum_l F[l,jj]*kv[b,l,h,d] ---- */
__global__ void __launch_bounds__(256) k_stageA() {
    const int bh = blockIdx.x, b = bh >> 4, h = bh & 15;
    const int lbase0 = blockIdx.y * 256;
    const int tid = threadIdx.x, tx = tid & 15, ty = tid >> 4;
    __shared__ __align__(16) float F[16][64];
    __shared__ __align__(16) float KV[16][64];
    float acc[4][4] = {};
    for (int sub = 0; sub < 16; sub++) {
        int lbase = lbase0 + sub * 16;
        *(float4*)&F[ty][tx*4]  = *(const float4*)(g_F + (size_t)(lbase + ty) * 64 + tx * 4);
        *(float4*)&KV[ty][tx*4] = *(const float4*)(g_kv + (size_t)(b * TT + lbase + ty) * DIMM + h * 64 + tx * 4);
        __syncthreads();
        #pragma unroll
        for (int l = 0; l < 16; l++) {
            float4 f4 = *(const float4*)&F[l][ty * 4];
            float4 k4 = *(const float4*)&KV[l][tx * 4];
            float ff[4] = {f4.x, f4.y, f4.z, f4.w};
            float kk[4] = {k4.x, k4.y, k4.z, k4.w};
            #pragma unroll
            for (int i = 0; i < 4; i++)
                #pragma unroll
                for (int j = 0; j < 4; j++) acc[i][j] += ff[i] * kk[j];
        }
        __syncthreads();
    }
    float* Pp = g_P + (size_t)bh * 4096;
    #pragma unroll
    for (int i = 0; i < 4; i++)
        #pragma unroll
        for (int j = 0; j < 4; j++)
            atomicAdd(&Pp[(ty*4 + i) * 64 + tx*4 + j], acc[i][j]);
}

/* ---- stage B: loading = G . P -> fp16 A for output GEMM ---- */
__global__ void __launch_bounds__(256) k_stageB() {
    const int base = blockIdx.x * 32;
    const int b = base / TT, t0 = base - b * TT;
    const int tid = threadIdx.x, tx = tid & 15, ty = tid >> 4;
    __shared__ __align__(16) float Ph[64][64];
    __shared__ __align__(16) float Gs[32][68];
    for (int h = 0; h < HH; h++) {
        for (int e = tid; e < 32 * 16; e += 256) {
            int tl = e >> 4, j4 = (e & 15) * 4;
            *(float4*)&Gs[tl][j4] = *(const float4*)(g_G + (size_t)((t0 + tl) * HH + h) * 64 + j4);
        }
        for (int e = tid; e < 1024; e += 256)
            ((float4*)Ph)[e] = ((const float4*)(g_P + (size_t)(b * HH + h) * 4096))[e];
        __syncthreads();
        float acc[2][4] = {};
        #pragma unroll
        for (int jj = 0; jj < 64; jj++) {
            float g0 = Gs[ty*2 + 0][jj];
            float g1 = Gs[ty*2 + 1][jj];
            float4 p = *(const float4*)&Ph[jj][tx * 4];
            acc[0][0] += g0*p.x; acc[0][1] += g0*p.y; acc[0][2] += g0*p.z; acc[0][3] += g0*p.w;
            acc[1][0] += g1*p.x; acc[1][1] += g1*p.y; acc[1][2] += g1*p.z; acc[1][3] += g1*p.w;
        }
        #pragma unroll
        for (int i = 0; i < 2; i++) {
            int row = base + ty*2 + i;
            float4 o = make_float4(acc[i][0], acc[i][1], acc[i][2], acc[i][3]);
            store_h4(g_loads + (size_t)row * TKE + h * 64 + tx * 4, o);
        }
        __syncthreads();
    }
}

extern "C" void kernel_launch(void* const* d_in, const int* in_sizes, int n_in,
                              void* d_out, int out_size) {
    const float* states = (const float*)d_in[0];
    const int*   mask   = (const int*)  d_in[1];
    const float* lnw    = (const float*)d_in[2];
    const float* angles = (const float*)d_in[3];
    const float* hdelta = (const float*)d_in[4];
    const float* Wk = (const float*)d_in[7];
    const float* bk = (const float*)d_in[8];
    const float* Wv = (const float*)d_in[9];
    const float* bv = (const float*)d_in[10];
    const float* Wo = (const float*)d_in[11];
    const float* bo = (const float*)d_in[12];
    float* out = (float*)d_out;

    cudaFuncSetAttribute(k_mma, cudaFuncAttributeMaxDynamicSharedMemorySize, GSMEM);

    k_convw<<<3072, 256>>>(Wk, Wv, Wo);
    k_trig<<<TT, 256>>>(angles, hdelta);
    k_rmsnorm<<<MM, 256>>>(states, lnw);

    dim3 gkv(MM / 128, HH);
    k_mma<<<gkv, 256, GSMEM>>>(0, nullptr, nullptr, bk, bv, mask);

    k_zeroP<<<(BB * HH * 64 * 64) / 256, 256>>>();
    dim3 ga(BB * HH, 8);
    k_stageA<<<ga, 256>>>();
    k_stageB<<<MM / 32, 256>>>();

    dim3 go(MM / 128, DIMM / 128);
    k_mma<<<go, 256, GSMEM>>>(1, out, bo, nullptr, nullptr, nullptr);
}